// round 16
// baseline (speedup 1.0000x reference)
#include <cuda_runtime.h>
#include <stdint.h>

#define N_ANTS   16384
#define N_NODES  512
#define N_BATCH  4096
#define N_STEPS  511   // N_NODES - 1

// Scratch (no allocation allowed -> __device__ globals)
__device__ uint2  g_subkeys[N_STEPS];
__device__ int    g_paths[N_ANTS * N_NODES];
__device__ float  g_plen[N_ANTS];
__device__ int    g_best;
__device__ int    g_ctr;                 // work-stealing counter (reset by keygen)
__device__ volatile uint32_t g_one = 1u; // opaque 1: forces adds onto IMAD (fma pipe)

// ---------- exact helpers (keygen + rare path; pipe placement irrelevant) ----
__device__ __forceinline__ void tfr_w(uint32_t& x0, uint32_t& x1, int R) {
    x0 += x1;
    unsigned long long w = (unsigned long long)x1 * (unsigned long long)(1u << R);
    x1 = ((uint32_t)w | (uint32_t)(w >> 32)) ^ x0;
}
__device__ __forceinline__ void threefry2x32(uint32_t ks0, uint32_t ks1, uint32_t ks2,
                                             uint32_t x0, uint32_t x1,
                                             uint32_t& o0, uint32_t& o1)
{
    x0 += ks0; x1 += ks1;
    tfr_w(x0, x1, 13); tfr_w(x0, x1, 15); tfr_w(x0, x1, 26); tfr_w(x0, x1, 6);
    x0 += ks1; x1 += ks2 + 1u;
    tfr_w(x0, x1, 17); tfr_w(x0, x1, 29); tfr_w(x0, x1, 16); tfr_w(x0, x1, 24);
    x0 += ks2; x1 += ks0 + 2u;
    tfr_w(x0, x1, 13); tfr_w(x0, x1, 15); tfr_w(x0, x1, 26); tfr_w(x0, x1, 6);
    x0 += ks0; x1 += ks1 + 3u;
    tfr_w(x0, x1, 17); tfr_w(x0, x1, 29); tfr_w(x0, x1, 16); tfr_w(x0, x1, 24);
    x0 += ks1; x1 += ks2 + 4u;
    tfr_w(x0, x1, 13); tfr_w(x0, x1, 15); tfr_w(x0, x1, 26); tfr_w(x0, x1, 6);
    x0 += ks2; x1 += ks0 + 5u;
    o0 = x0; o1 = x1;
}

// ---------- hot path: pipe-balanced threefry (champion R9 body, untouched) ---
// addf: a + b via IMAD.LO with an opaque multiplier -> guaranteed fma pipe.
__device__ __forceinline__ uint32_t addf(uint32_t a, uint32_t b, uint32_t one) {
    return a * one + b;
}
// SHF round, add forced to fma: IMAD(fma) + SHF(alu) + LOP3(alu)
__device__ __forceinline__ void tfr_sf(uint32_t& x0, uint32_t& x1, int R, uint32_t one) {
    x0 = addf(x0, x1, one);
    x1 = __funnelshift_l(x1, x1, R) ^ x0;
}
// wide-mul round, add forced to fma: IMAD(fma) + IMAD.WIDE(fma) + LOP3(alu)
__device__ __forceinline__ void tfr_wf(uint32_t& x0, uint32_t& x1, int R, uint32_t one) {
    x0 = addf(x0, x1, one);
    unsigned long long w = (unsigned long long)x1 * (unsigned long long)(1u << R);
    x1 = ((uint32_t)w | (uint32_t)(w >> 32)) ^ x0;
}

struct TFKeys {
    uint32_t i0;             // ks0 (x0 after inject 0)
    uint32_t c11, c12;       // ks1, ks2+1
    uint32_t c21, c22;       // ks2, ks0+2
    uint32_t c31, c32;       // ks0, ks1+3
    uint32_t c41, c42;       // ks1, ks2+4
    uint32_t c51, c52;       // ks2, ks0+5
};
// x=4 wide rounds (first of groups 1-4), 16 SHF rounds, all adds on fma pipe.
__device__ __forceinline__ uint32_t tf_bits(const TFKeys& k, uint32_t x1, uint32_t one)
{
    uint32_t x0 = k.i0;
    tfr_wf(x0, x1, 13, one); tfr_sf(x0, x1, 15, one); tfr_sf(x0, x1, 26, one); tfr_sf(x0, x1, 6, one);
    x0 = addf(x0, k.c11, one); x1 = addf(x1, k.c12, one);
    tfr_wf(x0, x1, 17, one); tfr_sf(x0, x1, 29, one); tfr_sf(x0, x1, 16, one); tfr_sf(x0, x1, 24, one);
    x0 = addf(x0, k.c21, one); x1 = addf(x1, k.c22, one);
    tfr_wf(x0, x1, 13, one); tfr_sf(x0, x1, 15, one); tfr_sf(x0, x1, 26, one); tfr_sf(x0, x1, 6, one);
    x0 = addf(x0, k.c31, one); x1 = addf(x1, k.c32, one);
    tfr_wf(x0, x1, 17, one); tfr_sf(x0, x1, 29, one); tfr_sf(x0, x1, 16, one); tfr_sf(x0, x1, 24, one);
    x0 = addf(x0, k.c41, one); x1 = addf(x1, k.c42, one);
    tfr_sf(x0, x1, 13, one); tfr_sf(x0, x1, 15, one); tfr_sf(x0, x1, 26, one); tfr_sf(x0, x1, 6, one);
    x0 = addf(x0, k.c51, one); x1 = addf(x1, k.c52, one);
    return x0 ^ x1;          // y0 ^ y1 (JAX 32-bit random_bits)
}

// Sequential key chain; also resets the work-stealing counter.
__global__ void keygen_kernel()
{
    if (threadIdx.x != 0) return;
    g_ctr = 0;
    uint32_t k0 = 0u, k1 = 42u;
    for (int t = 0; t < N_STEPS; t++) {
        uint32_t ks2 = k0 ^ k1 ^ 0x1BD11BDAu;
        uint32_t n0, n1, s0, s1;
        threefry2x32(k0, k1, ks2, 0u, 0u, n0, n1);
        threefry2x32(k0, k1, ks2, 0u, 1u, s0, s1);
        g_subkeys[t] = make_uint2(s0, s1);
        k0 = n0; k1 = n1;
    }
}

// One warp per ant (work-stealing), persistent over all 511 steps. 16 nodes/lane.
// Occupancy probe: 4 blocks/SM (8 warps/SMSP), j-loop unrolled 8 to fit 64 regs.
__global__ void __launch_bounds__(256, 4) ants_kernel(const float* __restrict__ pher,
                                                      const float* __restrict__ heur,
                                                      const int*   __restrict__ pos)
{
    __shared__ uint2 s_subkeys[N_STEPS];
    for (int i = threadIdx.x; i < N_STEPS; i += blockDim.x)
        s_subkeys[i] = g_subkeys[i];
    __syncthreads();

    const uint32_t one = g_one;                    // opaque 1 (never folds)
    const int lane = threadIdx.x & 31;
    const int nbase = lane * 16;
    // Packed index complement: K = (31-lane)*16 + 15 ; K - j == K ^ j for j in [0,16)
    const uint32_t K = (uint32_t)((31 - lane) * 16 + 15);
    const float TINYF = 1.17549435e-38f;           // FLT_MIN (jax uniform minval)

    for (;;) {
        int a;
        if (lane == 0) a = atomicAdd(&g_ctr, 1);
        a = __shfl_sync(0xFFFFFFFFu, a, 0);
        if (a >= N_ANTS) break;

        const int p = pos[a];
        uint32_t vis = 0u;
        if ((p >> 4) == lane) vis |= 1u << (p & 15);
        int cur = p;
        float plen = 0.0f;
        if (lane == 0) g_paths[a * N_NODES] = p;

        const uint32_t idx0 = (uint32_t)a * N_NODES + (uint32_t)nbase;

        for (int step = 0; step < N_STEPS; step++) {
            const uint2 sk = s_subkeys[step];
            const uint32_t ks0 = sk.x, ks1 = sk.y;
            const uint32_t ks2 = ks0 ^ ks1 ^ 0x1BD11BDAu;
            TFKeys k;
            k.i0  = ks0;
            k.c11 = ks1; k.c12 = ks2 + 1u;
            k.c21 = ks2; k.c22 = ks0 + 2u;
            k.c31 = ks0; k.c32 = ks1 + 3u;
            k.c41 = ks1; k.c42 = ks2 + 4u;
            k.c51 = ks2; k.c52 = ks0 + 5u;
            const uint32_t b1 = idx0 + ks1;        // x1 base (inject 0 folded)

            // Top-2 of packed keys: high 23 bits = mantissa, low 9 = 511-n
            uint32_t p1 = 0u, p2 = 0u;
#pragma unroll 8
            for (int j = 0; j < 16; j++) {
                const uint32_t bits = tf_bits(k, addf(b1, (uint32_t)j, one), one);
                const uint32_t pk = (bits & 0xFFFFFE00u) | (K ^ (uint32_t)j);
                const uint32_t t = min(p1, pk);
                p1 = max(p1, pk);
                p2 = max(p2, t);
            }

            // Warp top-2 via REDUX: packed keys are globally distinct (index bits),
            // so exactly one lane holds g1; its p2 substitutes for the g2 reduce.
            const uint32_t g1 = __reduce_max_sync(0xFFFFFFFFu, p1);
            const uint32_t cand = (p1 == g1) ? p2 : p1;
            const uint32_t g2 = __reduce_max_sync(0xFFFFFFFFu, cand);

            int nxt;
            // Integer-only conservative fast-path test (proved against the R1
            // e^0.002 margin): safe when m1-m2 >= ~0.0022*(2^23 - m1).
            const uint32_t m1 = g1 >> 9, m2 = g2 >> 9;
            const uint32_t d = 0x800000u - m1;
            const uint32_t thr = (d >> 9) + (d >> 12) + 4u;
            if (m1 - m2 >= thr) {
                nxt = 511 - (int)(g1 & 0x1FFu);
            } else {
                // Exact reference computation (rare: ~0.2% of ant-steps).
                float best = -__int_as_float(0x7f800000);  // -inf
                int  besti = N_NODES;
#pragma unroll 4
                for (int j = 0; j < 16; j++) {
                    const int n = nbase + j;
                    uint32_t o0, o1;
                    threefry2x32(ks0, ks1, ks2, 0u, idx0 + (uint32_t)j, o0, o1);
                    const uint32_t mm = (o0 ^ o1) >> 9;
                    const float f = __uint_as_float(mm | 0x3f800000u) - 1.0f;
                    const float u = fmaxf(f, TINYF);
                    const float g = -logf(-logf(u));
                    const float h = __ldg(&heur[p * N_NODES + n]);
                    const float b = __ldg(&pher[p * N_NODES + n]) * (h * h);
                    const float l = ((vis >> j) & 1u) ? 0.0f : b;
                    const float s = g + l;
                    if (s > best) { best = s; besti = n; }  // first-index tie-break
                }
#pragma unroll
                for (int ofs = 16; ofs > 0; ofs >>= 1) {
                    const float ob = __shfl_xor_sync(0xFFFFFFFFu, best, ofs);
                    const int   oi = __shfl_xor_sync(0xFFFFFFFFu, besti, ofs);
                    if (ob > best || (ob == best && oi < besti)) { best = ob; besti = oi; }
                }
                nxt = besti;
            }

            // plen accumulation in exact reference order (every lane, same value)
            plen += __ldg(&heur[cur * N_NODES + nxt]);
            if ((nxt >> 4) == lane) vis |= 1u << (nxt & 15);
            if (lane == 0) g_paths[a * N_NODES + step + 1] = nxt;
            cur = nxt;
        }
        if (lane == 0) g_plen[a] = plen;
    }
}

// First-index argmin over 16384 path lengths
__global__ void argmin_kernel()
{
    __shared__ float sv[1024];
    __shared__ int   si[1024];
    const int t = threadIdx.x;
    float bv = __int_as_float(0x7f800000);  // +inf
    int   bi = 0x7fffffff;
    for (int i = t; i < N_ANTS; i += 1024) {
        const float v = g_plen[i];
        if (v < bv || (v == bv && i < bi)) { bv = v; bi = i; }
    }
    sv[t] = bv; si[t] = bi;
    __syncthreads();
    for (int s = 512; s > 0; s >>= 1) {
        if (t < s) {
            const float ov = sv[t + s]; const int oi = si[t + s];
            if (ov < sv[t] || (ov == sv[t] && oi < si[t])) { sv[t] = ov; si[t] = oi; }
        }
        __syncthreads();
    }
    if (t == 0) g_best = si[0];
}

__global__ void bcast_kernel(float* __restrict__ out)
{
    const int i = blockIdx.x * blockDim.x + threadIdx.x;
    if (i < N_BATCH * N_NODES) {
        const int n = i & (N_NODES - 1);
        out[i] = (float)g_paths[g_best * N_NODES + n];
    }
}

extern "C" void kernel_launch(void* const* d_in, const int* in_sizes, int n_in,
                              void* d_out, int out_size)
{
    // metadata order: x, pheromone_trails, heuristic_info, ant_positions
    const float* pher = (const float*)d_in[1];
    const float* heur = (const float*)d_in[2];
    const int*   pos  = (const int*)d_in[3];
    float* out = (float*)d_out;

    keygen_kernel<<<1, 32>>>();
    ants_kernel<<<1184, 256>>>(pher, heur, pos);   // work-stealing grid
    argmin_kernel<<<1, 1024>>>();
    bcast_kernel<<<(N_BATCH * N_NODES + 255) / 256, 256>>>(out);
}

// round 17
// speedup vs baseline: 1.0793x; 1.0793x over previous
#include <cuda_runtime.h>
#include <stdint.h>

#define N_ANTS   16384
#define N_NODES  512
#define N_BATCH  4096
#define N_STEPS  511   // N_NODES - 1

// ---------------- compile-time subkey table ----------------------------------
// The JAX key chain key(42) -> 511x (new_key, subkey) depends only on the seed,
// so evaluate the whole threefry split-chain at compile time.
struct KeyTab { uint32_t x[N_STEPS]; uint32_t y[N_STEPS]; };
struct TFOut { uint32_t a, b; };

constexpr uint32_t rotl_c(uint32_t v, int r) { return (v << r) | (v >> (32 - r)); }

constexpr TFOut tf_c(uint32_t ks0, uint32_t ks1, uint32_t ks2,
                     uint32_t x0, uint32_t x1)
{
    const int rot[8] = {13, 15, 26, 6, 17, 29, 16, 24};
    x0 += ks0; x1 += ks1;
    for (int g = 0; g < 5; g++) {
        const int* rs = (g % 2 == 0) ? rot : rot + 4;
        for (int r = 0; r < 4; r++) {
            x0 += x1;
            x1 = rotl_c(x1, rs[r]) ^ x0;
        }
        // key injection after each group of 4 rounds
        const uint32_t inj0[5] = {ks1, ks2, ks0, ks1, ks2};
        const uint32_t inj1[5] = {ks2, ks0, ks1, ks2, ks0};
        x0 += inj0[g];
        x1 += inj1[g] + (uint32_t)(g + 1);
    }
    return TFOut{x0, x1};
}

constexpr KeyTab make_keytab()
{
    KeyTab t{};
    uint32_t k0 = 0u, k1 = 42u;
    for (int i = 0; i < N_STEPS; i++) {
        const uint32_t ks2 = k0 ^ k1 ^ 0x1BD11BDAu;
        const TFOut nk = tf_c(k0, k1, ks2, 0u, 0u);   // new_key
        const TFOut sk = tf_c(k0, k1, ks2, 0u, 1u);   // subkey
        t.x[i] = sk.a; t.y[i] = sk.b;
        k0 = nk.a; k1 = nk.b;
    }
    return t;
}

__device__ constexpr KeyTab C_KEYS = make_keytab();

// ---------------- scratch (no allocation allowed -> __device__ globals) ------
__device__ int    g_paths[N_ANTS * N_NODES];
__device__ float  g_plen[N_ANTS];
__device__ int    g_best;
__device__ int    g_ctr = 0;             // work-stealing counter (reset by bcast)
__device__ volatile uint32_t g_one = 1u; // opaque 1: forces adds onto IMAD (fma pipe)

// ---------- exact helpers (rare path) ----------------------------------------
__device__ __forceinline__ void tfr_w(uint32_t& x0, uint32_t& x1, int R) {
    x0 += x1;
    unsigned long long w = (unsigned long long)x1 * (unsigned long long)(1u << R);
    x1 = ((uint32_t)w | (uint32_t)(w >> 32)) ^ x0;
}
__device__ __forceinline__ void threefry2x32(uint32_t ks0, uint32_t ks1, uint32_t ks2,
                                             uint32_t x0, uint32_t x1,
                                             uint32_t& o0, uint32_t& o1)
{
    x0 += ks0; x1 += ks1;
    tfr_w(x0, x1, 13); tfr_w(x0, x1, 15); tfr_w(x0, x1, 26); tfr_w(x0, x1, 6);
    x0 += ks1; x1 += ks2 + 1u;
    tfr_w(x0, x1, 17); tfr_w(x0, x1, 29); tfr_w(x0, x1, 16); tfr_w(x0, x1, 24);
    x0 += ks2; x1 += ks0 + 2u;
    tfr_w(x0, x1, 13); tfr_w(x0, x1, 15); tfr_w(x0, x1, 26); tfr_w(x0, x1, 6);
    x0 += ks0; x1 += ks1 + 3u;
    tfr_w(x0, x1, 17); tfr_w(x0, x1, 29); tfr_w(x0, x1, 16); tfr_w(x0, x1, 24);
    x0 += ks1; x1 += ks2 + 4u;
    tfr_w(x0, x1, 13); tfr_w(x0, x1, 15); tfr_w(x0, x1, 26); tfr_w(x0, x1, 6);
    x0 += ks2; x1 += ks0 + 5u;
    o0 = x0; o1 = x1;
}

// ---------- hot path: pipe-balanced threefry (champion R9 body, untouched) ---
// addf: a + b via IMAD.LO with an opaque multiplier -> guaranteed fma pipe.
__device__ __forceinline__ uint32_t addf(uint32_t a, uint32_t b, uint32_t one) {
    return a * one + b;
}
// SHF round, add forced to fma: IMAD(fma) + SHF(alu) + LOP3(alu)
__device__ __forceinline__ void tfr_sf(uint32_t& x0, uint32_t& x1, int R, uint32_t one) {
    x0 = addf(x0, x1, one);
    x1 = __funnelshift_l(x1, x1, R) ^ x0;
}
// wide-mul round, add forced to fma: IMAD(fma) + IMAD.WIDE(fma) + LOP3(alu)
__device__ __forceinline__ void tfr_wf(uint32_t& x0, uint32_t& x1, int R, uint32_t one) {
    x0 = addf(x0, x1, one);
    unsigned long long w = (unsigned long long)x1 * (unsigned long long)(1u << R);
    x1 = ((uint32_t)w | (uint32_t)(w >> 32)) ^ x0;
}

struct TFKeys {
    uint32_t i0;             // ks0 (x0 after inject 0)
    uint32_t c11, c12;       // ks1, ks2+1
    uint32_t c21, c22;       // ks2, ks0+2
    uint32_t c31, c32;       // ks0, ks1+3
    uint32_t c41, c42;       // ks1, ks2+4
    uint32_t c51, c52;       // ks2, ks0+5
};
// x=4 wide rounds (first of groups 1-4), 16 SHF rounds, all adds on fma pipe.
__device__ __forceinline__ uint32_t tf_bits(const TFKeys& k, uint32_t x1, uint32_t one)
{
    uint32_t x0 = k.i0;
    tfr_wf(x0, x1, 13, one); tfr_sf(x0, x1, 15, one); tfr_sf(x0, x1, 26, one); tfr_sf(x0, x1, 6, one);
    x0 = addf(x0, k.c11, one); x1 = addf(x1, k.c12, one);
    tfr_wf(x0, x1, 17, one); tfr_sf(x0, x1, 29, one); tfr_sf(x0, x1, 16, one); tfr_sf(x0, x1, 24, one);
    x0 = addf(x0, k.c21, one); x1 = addf(x1, k.c22, one);
    tfr_wf(x0, x1, 13, one); tfr_sf(x0, x1, 15, one); tfr_sf(x0, x1, 26, one); tfr_sf(x0, x1, 6, one);
    x0 = addf(x0, k.c31, one); x1 = addf(x1, k.c32, one);
    tfr_wf(x0, x1, 17, one); tfr_sf(x0, x1, 29, one); tfr_sf(x0, x1, 16, one); tfr_sf(x0, x1, 24, one);
    x0 = addf(x0, k.c41, one); x1 = addf(x1, k.c42, one);
    tfr_sf(x0, x1, 13, one); tfr_sf(x0, x1, 15, one); tfr_sf(x0, x1, 26, one); tfr_sf(x0, x1, 6, one);
    x0 = addf(x0, k.c51, one); x1 = addf(x1, k.c52, one);
    return x0 ^ x1;          // y0 ^ y1 (JAX 32-bit random_bits)
}

// One warp per ant (work-stealing), persistent over all 511 steps. 16 nodes/lane.
__global__ void __launch_bounds__(256) ants_kernel(const float* __restrict__ pher,
                                                   const float* __restrict__ heur,
                                                   const int*   __restrict__ pos)
{
    __shared__ uint2 s_subkeys[N_STEPS];
    for (int i = threadIdx.x; i < N_STEPS; i += blockDim.x)
        s_subkeys[i] = make_uint2(C_KEYS.x[i], C_KEYS.y[i]);
    __syncthreads();

    const uint32_t one = g_one;                    // opaque 1 (never folds)
    const int lane = threadIdx.x & 31;
    const int nbase = lane * 16;
    // Packed index complement: K = (31-lane)*16 + 15 ; K - j == K ^ j for j in [0,16)
    const uint32_t K = (uint32_t)((31 - lane) * 16 + 15);
    const float TINYF = 1.17549435e-38f;           // FLT_MIN (jax uniform minval)

    for (;;) {
        int a;
        if (lane == 0) a = atomicAdd(&g_ctr, 1);
        a = __shfl_sync(0xFFFFFFFFu, a, 0);
        if (a >= N_ANTS) break;

        const int p = pos[a];
        uint32_t vis = 0u;
        if ((p >> 4) == lane) vis |= 1u << (p & 15);
        int cur = p;
        float plen = 0.0f;
        if (lane == 0) g_paths[a * N_NODES] = p;

        const uint32_t idx0 = (uint32_t)a * N_NODES + (uint32_t)nbase;

        for (int step = 0; step < N_STEPS; step++) {
            const uint2 sk = s_subkeys[step];
            const uint32_t ks0 = sk.x, ks1 = sk.y;
            const uint32_t ks2 = ks0 ^ ks1 ^ 0x1BD11BDAu;
            TFKeys k;
            k.i0  = ks0;
            k.c11 = ks1; k.c12 = ks2 + 1u;
            k.c21 = ks2; k.c22 = ks0 + 2u;
            k.c31 = ks0; k.c32 = ks1 + 3u;
            k.c41 = ks1; k.c42 = ks2 + 4u;
            k.c51 = ks2; k.c52 = ks0 + 5u;
            const uint32_t b1 = idx0 + ks1;        // x1 base (inject 0 folded)

            // Top-2 of packed keys: high 23 bits = mantissa, low 9 = 511-n
            uint32_t p1 = 0u, p2 = 0u;
#pragma unroll
            for (int j = 0; j < 16; j++) {
                const uint32_t bits = tf_bits(k, addf(b1, (uint32_t)j, one), one);
                const uint32_t pk = (bits & 0xFFFFFE00u) | (K ^ (uint32_t)j);
                const uint32_t t = min(p1, pk);
                p1 = max(p1, pk);
                p2 = max(p2, t);
            }

            // Warp top-2 via REDUX: packed keys are globally distinct (index bits),
            // so exactly one lane holds g1; its p2 substitutes for the g2 reduce.
            const uint32_t g1 = __reduce_max_sync(0xFFFFFFFFu, p1);
            const uint32_t cand = (p1 == g1) ? p2 : p1;
            const uint32_t g2 = __reduce_max_sync(0xFFFFFFFFu, cand);

            int nxt;
            // Integer-only conservative fast-path test (proved against the R1
            // e^0.002 margin): safe when m1-m2 >= ~0.0022*(2^23 - m1).
            const uint32_t m1 = g1 >> 9, m2 = g2 >> 9;
            const uint32_t d = 0x800000u - m1;
            const uint32_t thr = (d >> 9) + (d >> 12) + 4u;
            if (m1 - m2 >= thr) {
                nxt = 511 - (int)(g1 & 0x1FFu);
            } else {
                // Exact reference computation (rare: ~0.2% of ant-steps).
                float best = -__int_as_float(0x7f800000);  // -inf
                int  besti = N_NODES;
#pragma unroll
                for (int j = 0; j < 16; j++) {
                    const int n = nbase + j;
                    uint32_t o0, o1;
                    threefry2x32(ks0, ks1, ks2, 0u, idx0 + (uint32_t)j, o0, o1);
                    const uint32_t mm = (o0 ^ o1) >> 9;
                    const float f = __uint_as_float(mm | 0x3f800000u) - 1.0f;
                    const float u = fmaxf(f, TINYF);
                    const float g = -logf(-logf(u));
                    const float h = __ldg(&heur[p * N_NODES + n]);
                    const float b = __ldg(&pher[p * N_NODES + n]) * (h * h);
                    const float l = ((vis >> j) & 1u) ? 0.0f : b;
                    const float s = g + l;
                    if (s > best) { best = s; besti = n; }  // first-index tie-break
                }
#pragma unroll
                for (int ofs = 16; ofs > 0; ofs >>= 1) {
                    const float ob = __shfl_xor_sync(0xFFFFFFFFu, best, ofs);
                    const int   oi = __shfl_xor_sync(0xFFFFFFFFu, besti, ofs);
                    if (ob > best || (ob == best && oi < besti)) { best = ob; besti = oi; }
                }
                nxt = besti;
            }

            // plen accumulation in exact reference order (every lane, same value)
            plen += __ldg(&heur[cur * N_NODES + nxt]);
            if ((nxt >> 4) == lane) vis |= 1u << (nxt & 15);
            if (lane == 0) g_paths[a * N_NODES + step + 1] = nxt;
            cur = nxt;
        }
        if (lane == 0) g_plen[a] = plen;
    }
}

// First-index argmin over 16384 path lengths
__global__ void argmin_kernel()
{
    __shared__ float sv[1024];
    __shared__ int   si[1024];
    const int t = threadIdx.x;
    float bv = __int_as_float(0x7f800000);  // +inf
    int   bi = 0x7fffffff;
    for (int i = t; i < N_ANTS; i += 1024) {
        const float v = g_plen[i];
        if (v < bv || (v == bv && i < bi)) { bv = v; bi = i; }
    }
    sv[t] = bv; si[t] = bi;
    __syncthreads();
    for (int s = 512; s > 0; s >>= 1) {
        if (t < s) {
            const float ov = sv[t + s]; const int oi = si[t + s];
            if (ov < sv[t] || (ov == sv[t] && oi < si[t])) { sv[t] = ov; si[t] = oi; }
        }
        __syncthreads();
    }
    if (t == 0) g_best = si[0];
}

// Broadcast best path; thread 0 also resets the work-stealing counter so the
// next replay (or the initial load-time 0) always sees g_ctr == 0 before ants.
__global__ void bcast_kernel(float* __restrict__ out)
{
    const int i = blockIdx.x * blockDim.x + threadIdx.x;
    if (i == 0) g_ctr = 0;
    if (i < N_BATCH * N_NODES) {
        const int n = i & (N_NODES - 1);
        out[i] = (float)g_paths[g_best * N_NODES + n];
    }
}

extern "C" void kernel_launch(void* const* d_in, const int* in_sizes, int n_in,
                              void* d_out, int out_size)
{
    // metadata order: x, pheromone_trails, heuristic_info, ant_positions
    const float* pher = (const float*)d_in[1];
    const float* heur = (const float*)d_in[2];
    const int*   pos  = (const int*)d_in[3];
    float* out = (float*)d_out;

    ants_kernel<<<1184, 256>>>(pher, heur, pos);   // work-stealing grid
    argmin_kernel<<<1, 1024>>>();
    bcast_kernel<<<(N_BATCH * N_NODES + 255) / 256, 256>>>(out);
}